// round 14
// baseline (speedup 1.0000x reference)
#include <cuda_runtime.h>
#include <math.h>
#include <stdint.h>

#define NN 100000
#define NE 1600000
#define NB 64
#define FI 16
#define HD 128
#define GF 8
#define F19 19
#define F20 20
#define BN_EPS 1e-5f
#define SCAN_BS 1024
#define SCAN_NBLK ((NN + SCAN_BS - 1) / SCAN_BS)   // 98
#define GH_SMEM 65536                               // k_gemmH dynamic smem
#define APX 132                                     // fused-A smem row stride (mult of 4!)
#define GG_SMEM ((128 * APX + 2 * 32 * 128) * 4)    // 100352 B
#define GB_H ((NN + 127) / 128)                     // 782

typedef unsigned long long ull;

// ---------------- scratch (device globals: allocation-free) ----------------
__device__ float g_x19 [NN * F20];
__device__ float g_h   [NN * HD];
__device__ float g_xA  [NN * HD];
__device__ float g_xB  [NN * HD];
__device__ float g_stats[2 * HD];
__device__ float g_coef [2 * HD];
__device__ int   g_ctr;
__device__ int   g_gstart[NB + 1];
__device__ float g_pooled[NB * 2 * HD];
// CSR scratch
__device__ int g_deg[NN];
__device__ int g_rowstart[NN + 1];
__device__ int g_cursor[NN];
__device__ int g_esrc[NE];
__device__ int g_bsum[SCAN_NBLK];

// ---------------- helpers ----------------
__device__ __forceinline__ float elu01(float v) {
    return v > 0.f ? v : 0.1f * expm1f(v);
}
__device__ __forceinline__ void ffma2(ull& d, ull a, ull b) {
    asm("fma.rn.f32x2 %0, %1, %2, %0;" : "+l"(d) : "l"(a), "l"(b));
}
__device__ __forceinline__ ull dup2(float a) {
    ull r; asm("mov.b64 %0, {%1, %1};" : "=l"(r) : "f"(a)); return r;
}
__device__ __forceinline__ ull pk2(float x, float y) {
    ull r; asm("mov.b64 %0, {%1, %2};" : "=l"(r) : "f"(x), "f"(y)); return r;
}
__device__ __forceinline__ float2 upk(ull v) {
    float2 f; asm("mov.b64 {%0, %1}, %2;" : "=f"(f.x), "=f"(f.y) : "l"(v)); return f;
}
__device__ __forceinline__ uint32_t smem_u32(const void* p) {
    return (uint32_t)__cvta_generic_to_shared(p);
}
__device__ __forceinline__ void cp16(uint32_t dst, const void* src) {
    asm volatile("cp.async.ca.shared.global [%0], [%1], 16;" :: "r"(dst), "l"(src) : "memory");
}

// stats -> BN coef epilogue; scr = 16*128 float smem scratch
template <int GRID>
__device__ __forceinline__ void stats_epilogue(
    float* scr, const float* cS, const float* cQ, int tid, int tx, int ty,
    const float* gm, const float* bt) {
    __syncthreads();
#pragma unroll
    for (int c = 0; c < 8; c++) scr[ty * 128 + tx * 8 + c] = cS[c];
    __syncthreads();
    if (tid < 128) {
        float s = 0.f;
#pragma unroll
        for (int j = 0; j < 16; j++) s += scr[j * 128 + tid];
        atomicAdd(&g_stats[tid], s);
    }
    __syncthreads();
#pragma unroll
    for (int c = 0; c < 8; c++) scr[ty * 128 + tx * 8 + c] = cQ[c];
    __syncthreads();
    if (tid < 128) {
        float s = 0.f;
#pragma unroll
        for (int j = 0; j < 16; j++) s += scr[j * 128 + tid];
        atomicAdd(&g_stats[128 + tid], s);
    }
    __shared__ int s_last;
    __threadfence();
    __syncthreads();
    if (tid == 0) s_last = (atomicAdd(&g_ctr, 1) == GRID - 1) ? 1 : 0;
    __syncthreads();
    if (s_last) {
        __threadfence();
        if (tid < 128) {
            float mean = g_stats[tid] * (1.f / NN);
            float var = g_stats[128 + tid] * (1.f / NN) - mean * mean;
            float a = gm[tid] * rsqrtf(var + BN_EPS);
            g_coef[tid] = a;
            g_coef[128 + tid] = bt[tid] - mean * a;
            g_stats[tid] = 0.f;
            g_stats[128 + tid] = 0.f;
        }
        __threadfence();
        if (tid == 0) g_ctr = 0;
    }
}

// ---------------- CSR build ----------------
__global__ void k_bounds(const int* __restrict__ batch) {
    int i = blockIdx.x * blockDim.x + threadIdx.x;
    if (i < NN) g_deg[i] = 0;
    if (i < 256) g_stats[i] = 0.f;
    if (i == 0) { g_ctr = 0; g_rowstart[NN] = NE; }
    if (i >= NN) return;
    int cur = batch[i];
    int prev = (i == 0) ? -1 : batch[i - 1];
    for (int g = prev + 1; g <= cur; ++g) g_gstart[g] = i;
    if (i == NN - 1)
        for (int g = cur + 1; g <= NB; ++g) g_gstart[g] = NN;
}
__global__ void k_deg(const int* __restrict__ dst) {
    int e = blockIdx.x * blockDim.x + threadIdx.x;
    if (e < NE) atomicAdd(&g_deg[dst[e]], 1);
}
__global__ void k_scanA() {
    __shared__ int s[SCAN_BS];
    int i = blockIdx.x * SCAN_BS + threadIdx.x;
    int v = (i < NN) ? g_deg[i] : 0;
    s[threadIdx.x] = v;
    __syncthreads();
#pragma unroll
    for (int off = 1; off < SCAN_BS; off <<= 1) {
        int t = (threadIdx.x >= off) ? s[threadIdx.x - off] : 0;
        __syncthreads();
        s[threadIdx.x] += t;
        __syncthreads();
    }
    if (i < NN) g_rowstart[i] = s[threadIdx.x] - v;
    if (threadIdx.x == SCAN_BS - 1) g_bsum[blockIdx.x] = s[SCAN_BS - 1];
}
// scanC includes the 98-element block-sum prefix (warp 0 of each block)
__global__ void k_scanC() {
    __shared__ int pre[SCAN_NBLK];
    if (threadIdx.x < 32) {
        int lane = threadIdx.x;
        int carry = 0;
        for (int b0 = 0; b0 < SCAN_NBLK; b0 += 32) {
            int i = b0 + lane;
            int orig = (i < SCAN_NBLK) ? g_bsum[i] : 0;
            int v = orig;
#pragma unroll
            for (int o = 1; o < 32; o <<= 1) {
                int t = __shfl_up_sync(0xFFFFFFFFu, v, o);
                if (lane >= o) v += t;
            }
            int total = __shfl_sync(0xFFFFFFFFu, v, 31);
            if (i < SCAN_NBLK) pre[i] = v - orig + carry;
            carry += total;
        }
    }
    __syncthreads();
    int i = blockIdx.x * blockDim.x + threadIdx.x;
    if (i < NN) {
        int r = g_rowstart[i] + pre[i / SCAN_BS];
        g_rowstart[i] = r;
        g_cursor[i] = r;
    }
}
__global__ void k_fill(const int* __restrict__ src, const int* __restrict__ dst) {
    int e = blockIdx.x * blockDim.x + threadIdx.x;
    if (e < NE) {
        int pos = atomicAdd(&g_cursor[dst[e]], 1);
        g_esrc[pos] = src[e];
    }
}

// ---------------- feature prep ----------------
__global__ void k_concat(const float* __restrict__ h0, const float* __restrict__ coord) {
    int i = blockIdx.x * blockDim.x + threadIdx.x;
    if (i >= NN * F20) return;
    int n = i / F20, j = i - n * F20;
    float v = 0.f;
    if (j < FI)        v = h0[n * FI + j];
    else if (j < F19)  v = coord[n * 3 + (j - FI)];
    g_x19[i] = v;
}

// ---------------- fused gather + GEMM1 (K=19) + stats ----------------
__global__ void __launch_bounds__(256, 2)
k_gg19(const float* __restrict__ W, const float* __restrict__ bias,
       const float* __restrict__ gm, const float* __restrict__ bt,
       float* __restrict__ out) {
    __shared__ float As[20 * 128];   // [k][m]
    __shared__ float Bs[19 * 128];   // [k][n]
    const int tid = threadIdx.x;
    const int tx = tid & 15;
    const int ty = tid >> 4;
    const int m0 = blockIdx.x * 128;

    // W -> smem
    for (int i = tid; i < 19 * 32; i += 256)
        ((float4*)Bs)[i] = ((const float4*)W)[i];

    // gather 128 rows x 20 cols: 5 threads/node, each 4 cols
    for (int idx = tid; idx < 640; idx += 256) {
        int r = idx / 5;
        int c = (idx - r * 5) * 4;
        int node = m0 + r;
        float4 v = make_float4(0.f, 0.f, 0.f, 0.f);
        if (node < NN) {
            v = *(const float4*)&g_x19[node * F20 + c];
            int st = g_rowstart[node], en = g_rowstart[node + 1];
            for (int e = st; e < en; e++) {
                int s = g_esrc[e];
                float4 u = *(const float4*)&g_x19[s * F20 + c];
                v.x += u.x; v.y += u.y; v.z += u.z; v.w += u.w;
            }
        }
        As[(c + 0) * 128 + r] = v.x;
        As[(c + 1) * 128 + r] = v.y;
        As[(c + 2) * 128 + r] = v.z;
        As[(c + 3) * 128 + r] = v.w;
    }
    __syncthreads();

    ull acc[8][4];
#pragma unroll
    for (int r = 0; r < 8; r++)
#pragma unroll
        for (int c = 0; c < 4; c++) acc[r][c] = 0ull;

#pragma unroll
    for (int k = 0; k < F19; k++) {
        float4 a0 = *(const float4*)&As[k * 128 + ty * 8];
        float4 a1 = *(const float4*)&As[k * 128 + ty * 8 + 4];
        float4 b0 = *(const float4*)&Bs[k * 128 + tx * 8];
        float4 b1 = *(const float4*)&Bs[k * 128 + tx * 8 + 4];
        ull bp0 = pk2(b0.x, b0.y), bp1 = pk2(b0.z, b0.w);
        ull bp2 = pk2(b1.x, b1.y), bp3 = pk2(b1.z, b1.w);
        float arr[8] = {a0.x, a0.y, a0.z, a0.w, a1.x, a1.y, a1.z, a1.w};
#pragma unroll
        for (int r = 0; r < 8; r++) {
            ull ap = dup2(arr[r]);
            ffma2(acc[r][0], ap, bp0);
            ffma2(acc[r][1], ap, bp1);
            ffma2(acc[r][2], ap, bp2);
            ffma2(acc[r][3], ap, bp3);
        }
    }

    float4 bb0 = *(const float4*)&bias[tx * 8];
    float4 bb1 = *(const float4*)&bias[tx * 8 + 4];
    float bv[8] = {bb0.x, bb0.y, bb0.z, bb0.w, bb1.x, bb1.y, bb1.z, bb1.w};
    float cS[8], cQ[8];
#pragma unroll
    for (int c = 0; c < 8; c++) { cS[c] = 0.f; cQ[c] = 0.f; }
#pragma unroll
    for (int r = 0; r < 8; r++) {
        int grow = m0 + ty * 8 + r;
        if (grow < NN) {
            float2 p0 = upk(acc[r][0]), p1 = upk(acc[r][1]);
            float2 p2 = upk(acc[r][2]), p3 = upk(acc[r][3]);
            float v[8] = {p0.x, p0.y, p1.x, p1.y, p2.x, p2.y, p3.x, p3.y};
#pragma unroll
            for (int c = 0; c < 8; c++) {
                v[c] += bv[c];
                cS[c] += v[c]; cQ[c] += v[c] * v[c];
            }
            *(float4*)&out[(size_t)grow * HD + tx * 8]     = make_float4(v[0], v[1], v[2], v[3]);
            *(float4*)&out[(size_t)grow * HD + tx * 8 + 4] = make_float4(v[4], v[5], v[6], v[7]);
        }
    }
    stats_epilogue<GB_H>(As, cS, cQ, tid, tx, ty, gm, bt);
}

// ---------------- fused gather + GEMM1 (K=128) + stats ----------------
// A gathered into smem [m][k] stride APX; B double-buffered cp.async
__global__ void __launch_bounds__(256, 2)
k_ggH(const float* __restrict__ x, const float* __restrict__ W,
      const float* __restrict__ bias,
      const float* __restrict__ gm, const float* __restrict__ bt,
      float* __restrict__ out) {
    extern __shared__ float sm[];
    float* As = sm;                  // [128][APX]
    float* Bsm = sm + 128 * APX;     // [2][32*128]

    const int tid = threadIdx.x;
    const int wid = tid >> 5, lane = tid & 31;
    const int tx = tid & 15, ty = tid >> 4;
    const int m0 = blockIdx.x * 128;

    // B tile 0 prefetch (overlaps gather)
#pragma unroll
    for (int p = 0; p < 4; p++) {
        int idx = p * 256 + tid;
        int kk = idx >> 5, n4 = idx & 31;
        cp16(smem_u32(&Bsm[kk * 128 + n4 * 4]), &W[(size_t)kk * HD + n4 * 4]);
    }
    asm volatile("cp.async.commit_group;" ::: "memory");

    // gather: warp per node, 16 nodes per warp; lane owns cols 4l..4l+3
#pragma unroll 1
    for (int it = 0; it < 16; it++) {
        int r = it * 8 + wid;
        int node = m0 + r;
        float4 v0 = make_float4(0.f, 0.f, 0.f, 0.f);
        if (node < NN) {
            int st = g_rowstart[node], en = g_rowstart[node + 1];
            v0 = *(const float4*)&x[(size_t)node * HD + lane * 4];
            float4 v1 = make_float4(0.f, 0.f, 0.f, 0.f);
            int e = st;
            for (; e + 1 < en; e += 2) {
                int s0 = g_esrc[e], s1 = g_esrc[e + 1];
                float4 u0 = *(const float4*)&x[(size_t)s0 * HD + lane * 4];
                float4 u1 = *(const float4*)&x[(size_t)s1 * HD + lane * 4];
                v0.x += u0.x; v0.y += u0.y; v0.z += u0.z; v0.w += u0.w;
                v1.x += u1.x; v1.y += u1.y; v1.z += u1.z; v1.w += u1.w;
            }
            if (e < en) {
                int s0 = g_esrc[e];
                float4 u0 = *(const float4*)&x[(size_t)s0 * HD + lane * 4];
                v0.x += u0.x; v0.y += u0.y; v0.z += u0.z; v0.w += u0.w;
            }
            v0.x += v1.x; v0.y += v1.y; v0.z += v1.z; v0.w += v1.w;
        }
        *(float4*)&As[r * APX + lane * 4] = v0;
    }
    asm volatile("cp.async.wait_group 0;" ::: "memory");
    __syncthreads();

    ull acc[8][4];
#pragma unroll
    for (int r = 0; r < 8; r++)
#pragma unroll
        for (int c = 0; c < 4; c++) acc[r][c] = 0ull;

#pragma unroll
    for (int kt = 0; kt < 4; kt++) {
        const float* Bc = Bsm + (kt & 1) * 4096;
        if (kt < 3) {
            const int k0n = (kt + 1) * 32;
            float* Bn = Bsm + ((kt + 1) & 1) * 4096;
#pragma unroll
            for (int p = 0; p < 4; p++) {
                int idx = p * 256 + tid;
                int kk = idx >> 5, n4 = idx & 31;
                cp16(smem_u32(&Bn[kk * 128 + n4 * 4]), &W[(size_t)(k0n + kk) * HD + n4 * 4]);
            }
            asm volatile("cp.async.commit_group;" ::: "memory");
        }
#pragma unroll
        for (int k2 = 0; k2 < 16; k2++) {
            const int k = kt * 32 + k2 * 2;
            float2 a[8];
#pragma unroll
            for (int i = 0; i < 8; i++)
                a[i] = *(const float2*)&As[(ty * 8 + i) * APX + k];
            float4 b00 = *(const float4*)&Bc[(k2 * 2) * 128 + tx * 8];
            float4 b01 = *(const float4*)&Bc[(k2 * 2) * 128 + tx * 8 + 4];
            float4 b10 = *(const float4*)&Bc[(k2 * 2 + 1) * 128 + tx * 8];
            float4 b11 = *(const float4*)&Bc[(k2 * 2 + 1) * 128 + tx * 8 + 4];
            ull bp00 = pk2(b00.x, b00.y), bp01 = pk2(b00.z, b00.w);
            ull bp02 = pk2(b01.x, b01.y), bp03 = pk2(b01.z, b01.w);
            ull bp10 = pk2(b10.x, b10.y), bp11 = pk2(b10.z, b10.w);
            ull bp12 = pk2(b11.x, b11.y), bp13 = pk2(b11.z, b11.w);
#pragma unroll
            for (int r = 0; r < 8; r++) {
                ull a0 = dup2(a[r].x);
                ull a1 = dup2(a[r].y);
                ffma2(acc[r][0], a0, bp00);
                ffma2(acc[r][1], a0, bp01);
                ffma2(acc[r][2], a0, bp02);
                ffma2(acc[r][3], a0, bp03);
                ffma2(acc[r][0], a1, bp10);
                ffma2(acc[r][1], a1, bp11);
                ffma2(acc[r][2], a1, bp12);
                ffma2(acc[r][3], a1, bp13);
            }
        }
        if (kt < 3) {
            asm volatile("cp.async.wait_group 0;" ::: "memory");
            __syncthreads();
        }
    }

    float4 bb0 = *(const float4*)&bias[tx * 8];
    float4 bb1 = *(const float4*)&bias[tx * 8 + 4];
    float bv[8] = {bb0.x, bb0.y, bb0.z, bb0.w, bb1.x, bb1.y, bb1.z, bb1.w};
    float cS[8], cQ[8];
#pragma unroll
    for (int c = 0; c < 8; c++) { cS[c] = 0.f; cQ[c] = 0.f; }
#pragma unroll
    for (int r = 0; r < 8; r++) {
        int grow = m0 + ty * 8 + r;
        if (grow < NN) {
            float2 p0 = upk(acc[r][0]), p1 = upk(acc[r][1]);
            float2 p2 = upk(acc[r][2]), p3 = upk(acc[r][3]);
            float v[8] = {p0.x, p0.y, p1.x, p1.y, p2.x, p2.y, p3.x, p3.y};
#pragma unroll
            for (int c = 0; c < 8; c++) {
                v[c] += bv[c];
                cS[c] += v[c]; cQ[c] += v[c] * v[c];
            }
            *(float4*)&out[(size_t)grow * HD + tx * 8]     = make_float4(v[0], v[1], v[2], v[3]);
            *(float4*)&out[(size_t)grow * HD + tx * 8 + 4] = make_float4(v[4], v[5], v[6], v[7]);
        }
    }
    stats_epilogue<GB_H>(Bsm, cS, cQ, tid, tx, ty, gm, bt);
}

// ---------------- GEMM2: k-tile 32, double-buffered, BN+relu on A, ELU out ----------------
__global__ void __launch_bounds__(256, 2)
k_gemmH(const float* __restrict__ A, const float* __restrict__ W,
        const float* __restrict__ bias, float* __restrict__ out) {
    extern __shared__ float sm[];
    float* Asm = sm;            // [2][32*128]
    float* Bsm = sm + 8192;     // [2][32*128]

    const int tid = threadIdx.x;
    const int tx = tid & 15;
    const int ty = tid >> 4;
    const int m0 = blockIdx.x * 128;
    const int ar = tid >> 1;
    const int aq0 = 4 * (tid & 1);

    ull acc[8][4];
#pragma unroll
    for (int r = 0; r < 8; r++)
#pragma unroll
        for (int c = 0; c < 4; c++) acc[r][c] = 0ull;

    float4 pa[4];
#pragma unroll
    for (int p = 0; p < 4; p++) {
        int grow = m0 + ar;
        pa[p] = (grow < NN) ? *(const float4*)&A[(size_t)grow * HD + (aq0 + p) * 4]
                            : make_float4(0.f, 0.f, 0.f, 0.f);
    }
#pragma unroll
    for (int p = 0; p < 4; p++) {
        int idx = p * 256 + tid;
        int kk = idx >> 5, n4 = idx & 31;
        cp16(smem_u32(&Bsm[kk * 128 + n4 * 4]), &W[(size_t)kk * HD + n4 * 4]);
    }
    asm volatile("cp.async.commit_group;" ::: "memory");
#pragma unroll
    for (int p = 0; p < 4; p++) {
        int q = aq0 + p;
        float4 v = pa[p];
        float4 ca = *(const float4*)&g_coef[q * 4];
        float4 cb = *(const float4*)&g_coef[128 + q * 4];
        v.x = fmaxf(fmaf(ca.x, v.x, cb.x), 0.f);
        v.y = fmaxf(fmaf(ca.y, v.y, cb.y), 0.f);
        v.z = fmaxf(fmaf(ca.z, v.z, cb.z), 0.f);
        v.w = fmaxf(fmaf(ca.w, v.w, cb.w), 0.f);
        Asm[(q * 4 + 0) * 128 + ar] = v.x;
        Asm[(q * 4 + 1) * 128 + ar] = v.y;
        Asm[(q * 4 + 2) * 128 + ar] = v.z;
        Asm[(q * 4 + 3) * 128 + ar] = v.w;
    }
    asm volatile("cp.async.wait_group 0;" ::: "memory");
    __syncthreads();

#pragma unroll
    for (int kt = 0; kt < 4; kt++) {
        const float* Ac = Asm + (kt & 1) * 4096;
        const float* Bc = Bsm + (kt & 1) * 4096;
        if (kt < 3) {
            const int k0n = (kt + 1) * 32;
            float* Bn = Bsm + ((kt + 1) & 1) * 4096;
#pragma unroll
            for (int p = 0; p < 4; p++) {
                int idx = p * 256 + tid;
                int kk = idx >> 5, n4 = idx & 31;
                cp16(smem_u32(&Bn[kk * 128 + n4 * 4]), &W[(size_t)(k0n + kk) * HD + n4 * 4]);
            }
            asm volatile("cp.async.commit_group;" ::: "memory");
#pragma unroll
            for (int p = 0; p < 4; p++) {
                int grow = m0 + ar;
                pa[p] = (grow < NN)
                    ? *(const float4*)&A[(size_t)grow * HD + k0n + (aq0 + p) * 4]
                    : make_float4(0.f, 0.f, 0.f, 0.f);
            }
        }
#pragma unroll
        for (int k = 0; k < 32; k++) {
            float4 a0 = *(const float4*)&Ac[k * 128 + ty * 8];
            float4 a1 = *(const float4*)&Ac[k * 128 + ty * 8 + 4];
            float4 b0 = *(const float4*)&Bc[k * 128 + tx * 8];
            float4 b1 = *(const float4*)&Bc[k * 128 + tx * 8 + 4];
            ull bp0 = pk2(b0.x, b0.y), bp1 = pk2(b0.z, b0.w);
            ull bp2 = pk2(b1.x, b1.y), bp3 = pk2(b1.z, b1.w);
            float arr[8] = {a0.x, a0.y, a0.z, a0.w, a1.x, a1.y, a1.z, a1.w};
#pragma unroll
            for (int r = 0; r < 8; r++) {
                ull ap = dup2(arr[r]);
                ffma2(acc[r][0], ap, bp0);
                ffma2(acc[r][1], ap, bp1);
                ffma2(acc[r][2], ap, bp2);
                ffma2(acc[r][3], ap, bp3);
            }
        }
        if (kt < 3) {
            const int k0n = (kt + 1) * 32;
            float* An = Asm + ((kt + 1) & 1) * 4096;
#pragma unroll
            for (int p = 0; p < 4; p++) {
                int q = aq0 + p;
                float4 v = pa[p];
                float4 ca = *(const float4*)&g_coef[k0n + q * 4];
                float4 cb = *(const float4*)&g_coef[128 + k0n + q * 4];
                v.x = fmaxf(fmaf(ca.x, v.x, cb.x), 0.f);
                v.y = fmaxf(fmaf(ca.y, v.y, cb.y), 0.f);
                v.z = fmaxf(fmaf(ca.z, v.z, cb.z), 0.f);
                v.w = fmaxf(fmaf(ca.w, v.w, cb.w), 0.f);
                An[(q * 4 + 0) * 128 + ar] = v.x;
                An[(q * 4 + 1) * 128 + ar] = v.y;
                An[(q * 4 + 2) * 128 + ar] = v.z;
                An[(q * 4 + 3) * 128 + ar] = v.w;
            }
            asm volatile("cp.async.wait_group 0;" ::: "memory");
        }
        __syncthreads();
    }

    float4 bb0 = *(const float4*)&bias[tx * 8];
    float4 bb1 = *(const float4*)&bias[tx * 8 + 4];
    float bv[8] = {bb0.x, bb0.y, bb0.z, bb0.w, bb1.x, bb1.y, bb1.z, bb1.w};
#pragma unroll
    for (int r = 0; r < 8; r++) {
        int grow = m0 + ty * 8 + r;
        if (grow < NN) {
            float2 p0 = upk(acc[r][0]), p1 = upk(acc[r][1]);
            float2 p2 = upk(acc[r][2]), p3 = upk(acc[r][3]);
            float v[8] = {p0.x, p0.y, p1.x, p1.y, p2.x, p2.y, p3.x, p3.y};
#pragma unroll
            for (int c = 0; c < 8; c++) v[c] = elu01(v[c] + bv[c]);
            *(float4*)&out[(size_t)grow * HD + tx * 8]     = make_float4(v[0], v[1], v[2], v[3]);
            *(float4*)&out[(size_t)grow * HD + tx * 8 + 4] = make_float4(v[4], v[5], v[6], v[7]);
        }
    }
}

// ---------------- pooling / classifier ----------------
__global__ void k_pool(const float* __restrict__ x) {
    __shared__ float ps[4][128];
    __shared__ float pm[4][128];
    int b = blockIdx.x;
    int rg = threadIdx.x >> 7, c = threadIdx.x & 127;
    int st = g_gstart[b], en = g_gstart[b + 1];
    float s = 0.f, m = -INFINITY;
    for (int r = st + rg; r < en; r += 4) {
        float v = x[(size_t)r * HD + c];
        s += v;
        m = fmaxf(m, v);
    }
    ps[rg][c] = s;
    pm[rg][c] = m;
    __syncthreads();
    if (rg == 0) {
        float ss = ps[0][c] + ps[1][c] + ps[2][c] + ps[3][c];
        float mm = fmaxf(fmaxf(pm[0][c], pm[1][c]), fmaxf(pm[2][c], pm[3][c]));
        int cnt = en - st;
        g_pooled[b * 256 + c] = ss / (float)(cnt > 0 ? cnt : 1);
        g_pooled[b * 256 + 128 + c] = mm;
    }
}

__global__ void k_cls(const float* __restrict__ g0,
                      const float* __restrict__ cw1, const float* __restrict__ cb1,
                      const float* __restrict__ cgm, const float* __restrict__ cbt,
                      const float* __restrict__ cw2, const float* __restrict__ cb2,
                      float* __restrict__ out) {
    __shared__ float zrow[8][264];
    __shared__ float h1[64][128];
    __shared__ float lg[64][2];
    int c = threadIdx.x;  // <<<1,128>>>

    for (int r0 = 0; r0 < 64; r0 += 8) {
        for (int idx = c; idx < 8 * 264; idx += 128) {
            int rr = idx / 264, k = idx - rr * 264;
            int r = r0 + rr;
            zrow[rr][k] = (k < 256) ? g_pooled[r * 256 + k] : g0[r * GF + (k - 256)];
        }
        __syncthreads();
        float acc[8];
#pragma unroll
        for (int rr = 0; rr < 8; rr++) acc[rr] = 0.f;
        for (int k = 0; k < 264; ++k) {
            float w = cw1[k * HD + c];
#pragma unroll
            for (int rr = 0; rr < 8; rr++) acc[rr] += zrow[rr][k] * w;
        }
        float bias = cb1[c];
#pragma unroll
        for (int rr = 0; rr < 8; rr++) h1[r0 + rr][c] = elu01(acc[rr] + bias);
        __syncthreads();
    }

    float s = 0.f, sq = 0.f;
    for (int r = 0; r < 64; r++) {
        float v = h1[r][c];
        s += v;
        sq += v * v;
    }
    float mean = s * (1.f / 64.f);
    float var = sq * (1.f / 64.f) - mean * mean;
    float a = cgm[c] * rsqrtf(var + BN_EPS);
    float bb = cbt[c] - mean * a;
    for (int r = 0; r < 64; r++) h1[r][c] = h1[r][c] * a + bb;
    __syncthreads();

    {
        int r = c >> 1, cls = c & 1;
        float l = cb2[cls];
        for (int k = 0; k < 128; k++) l += h1[r][k] * cw2[k * 2 + cls];
        lg[r][cls] = l;
    }
    __syncthreads();
    {
        int r = c >> 1, cls = c & 1;
        float l0 = lg[r][0], l1 = lg[r][1];
        float mx = fmaxf(l0, l1);
        float e0 = expf(l0 - mx), e1 = expf(l1 - mx);
        out[r * 2 + cls] = ((cls == 0) ? e0 : e1) / (e0 + e1);
    }
}

// ---------------- launch ----------------
extern "C" void kernel_launch(void* const* d_in, const int* in_sizes, int n_in,
                              void* d_out, int out_size) {
    const float* h0     = (const float*)d_in[0];
    const float* coord0 = (const float*)d_in[1];
    const float* g0     = (const float*)d_in[2];
    const int*   eidx   = (const int*)  d_in[3];
    const int*   batch  = (const int*)  d_in[4];
    const float* w1_0 = (const float*)d_in[5];
    const float* b1_0 = (const float*)d_in[6];
    const float* gm_0 = (const float*)d_in[7];
    const float* bt_0 = (const float*)d_in[8];
    const float* w2_0 = (const float*)d_in[9];
    const float* b2_0 = (const float*)d_in[10];
    const float* w1_r = (const float*)d_in[11];
    const float* b1_r = (const float*)d_in[12];
    const float* gm_r = (const float*)d_in[13];
    const float* bt_r = (const float*)d_in[14];
    const float* w2_r = (const float*)d_in[15];
    const float* b2_r = (const float*)d_in[16];
    const float* cw1  = (const float*)d_in[17];
    const float* cb1  = (const float*)d_in[18];
    const float* cgm  = (const float*)d_in[19];
    const float* cbt  = (const float*)d_in[20];
    const float* cw2  = (const float*)d_in[21];
    const float* cb2  = (const float*)d_in[22];

    const int* src = eidx;
    const int* dst = eidx + NE;

    float *h, *xA, *xB;
    cudaGetSymbolAddress((void**)&h,  g_h);
    cudaGetSymbolAddress((void**)&xA, g_xA);
    cudaGetSymbolAddress((void**)&xB, g_xB);

    cudaFuncSetAttribute(k_gemmH, cudaFuncAttributeMaxDynamicSharedMemorySize, GH_SMEM);
    cudaFuncSetAttribute(k_ggH,   cudaFuncAttributeMaxDynamicSharedMemorySize, GG_SMEM);

    // ---- CSR build ----
    k_bounds<<<(NN + 255) / 256, 256>>>(batch);
    k_deg<<<(NE + 255) / 256, 256>>>(dst);
    k_scanA<<<SCAN_NBLK, SCAN_BS>>>();
    k_scanC<<<(NN + 255) / 256, 256>>>();
    k_fill<<<(NE + 255) / 256, 256>>>(src, dst);

    // ---- layer 0 ----
    k_concat<<<(NN * F20 + 255) / 256, 256>>>(h0, coord0);
    k_gg19<<<GB_H, 256>>>(w1_0, b1_0, gm_0, bt_0, h);
    k_gemmH<<<GB_H, 256, GH_SMEM>>>(h, w2_0, b2_0, xA);

    // ---- layers 1..2 ----
    for (int i = 0; i < 2; i++) {
        const float* xin = (i == 0) ? xA : xB;
        float* xout      = (i == 0) ? xB : xA;
        k_ggH<<<GB_H, 256, GG_SMEM>>>(xin, w1_r + i * HD * HD, b1_r + i * HD,
                                      gm_r + i * HD, bt_r + i * HD, h);
        k_gemmH<<<GB_H, 256, GH_SMEM>>>(h, w2_r + i * HD * HD, b2_r + i * HD, xout);
    }

    // ---- pooling + classifier ----
    k_pool<<<NB, 512>>>(xA);
    k_cls<<<1, 128>>>(g0, cw1, cb1, cgm, cbt, cw2, cb2, (float*)d_out);
}

// round 15
// speedup vs baseline: 1.0206x; 1.0206x over previous
#include <cuda_runtime.h>
#include <math.h>
#include <stdint.h>

#define NN 100000
#define NE 1600000
#define NB 64
#define FI 16
#define HD 128
#define GF 8
#define F19 19
#define F20 20
#define BN_EPS 1e-5f
#define SCAN_BS 1024
#define SCAN_NBLK ((NN + SCAN_BS - 1) / SCAN_BS)   // 98
#define GH_SMEM 65536                               // k_gemmH dynamic smem
#define GB_H ((NN + 127) / 128)                     // 782

typedef unsigned long long ull;

// ---------------- scratch (device globals: allocation-free) ----------------
__device__ float g_x19 [NN * F20];
__device__ float g_xa19[NN * F20];
__device__ float g_h   [NN * HD];
__device__ float g_xagg[NN * HD];
__device__ float g_xA  [NN * HD];
__device__ float g_xB  [NN * HD];
__device__ float g_stats[2 * HD];
__device__ float g_coef [2 * HD];
__device__ int   g_ctr;
__device__ int   g_gstart[NB + 1];
__device__ float g_pooled[NB * 2 * HD];
// CSR scratch
__device__ int g_deg[NN];
__device__ int g_rowstart[NN + 1];
__device__ int g_cursor[NN];
__device__ int g_esrc[NE];
__device__ int g_bsum[SCAN_NBLK];

// ---------------- helpers ----------------
__device__ __forceinline__ float elu01(float v) {
    return v > 0.f ? v : 0.1f * expm1f(v);
}
__device__ __forceinline__ void ffma2(ull& d, ull a, ull b) {
    asm("fma.rn.f32x2 %0, %1, %2, %0;" : "+l"(d) : "l"(a), "l"(b));
}
__device__ __forceinline__ ull dup2(float a) {
    ull r; asm("mov.b64 %0, {%1, %1};" : "=l"(r) : "f"(a)); return r;
}
__device__ __forceinline__ ull pk2(float x, float y) {
    ull r; asm("mov.b64 %0, {%1, %2};" : "=l"(r) : "f"(x), "f"(y)); return r;
}
__device__ __forceinline__ float2 upk(ull v) {
    float2 f; asm("mov.b64 {%0, %1}, %2;" : "=f"(f.x), "=f"(f.y) : "l"(v)); return f;
}
__device__ __forceinline__ uint32_t smem_u32(const void* p) {
    return (uint32_t)__cvta_generic_to_shared(p);
}
__device__ __forceinline__ void cp16(uint32_t dst, const void* src) {
    asm volatile("cp.async.ca.shared.global [%0], [%1], 16;" :: "r"(dst), "l"(src) : "memory");
}

// stats -> BN coef epilogue; scr = 16*128 float smem scratch
template <int GRID>
__device__ __forceinline__ void stats_epilogue(
    float* scr, const float* cS, const float* cQ, int tid, int tx, int ty,
    const float* gm, const float* bt) {
    __syncthreads();
#pragma unroll
    for (int c = 0; c < 8; c++) scr[ty * 128 + tx * 8 + c] = cS[c];
    __syncthreads();
    if (tid < 128) {
        float s = 0.f;
#pragma unroll
        for (int j = 0; j < 16; j++) s += scr[j * 128 + tid];
        atomicAdd(&g_stats[tid], s);
    }
    __syncthreads();
#pragma unroll
    for (int c = 0; c < 8; c++) scr[ty * 128 + tx * 8 + c] = cQ[c];
    __syncthreads();
    if (tid < 128) {
        float s = 0.f;
#pragma unroll
        for (int j = 0; j < 16; j++) s += scr[j * 128 + tid];
        atomicAdd(&g_stats[128 + tid], s);
    }
    __shared__ int s_last;
    __threadfence();
    __syncthreads();
    if (tid == 0) s_last = (atomicAdd(&g_ctr, 1) == GRID - 1) ? 1 : 0;
    __syncthreads();
    if (s_last) {
        __threadfence();
        if (tid < 128) {
            float mean = g_stats[tid] * (1.f / NN);
            float var = g_stats[128 + tid] * (1.f / NN) - mean * mean;
            float a = gm[tid] * rsqrtf(var + BN_EPS);
            g_coef[tid] = a;
            g_coef[128 + tid] = bt[tid] - mean * a;
            g_stats[tid] = 0.f;
            g_stats[128 + tid] = 0.f;
        }
        __threadfence();
        if (tid == 0) g_ctr = 0;
    }
}

// ---------------- CSR build ----------------
__global__ void k_bounds(const int* __restrict__ batch) {
    int i = blockIdx.x * blockDim.x + threadIdx.x;
    if (i < NN) g_deg[i] = 0;
    if (i < 256) g_stats[i] = 0.f;
    if (i == 0) { g_ctr = 0; g_rowstart[NN] = NE; }
    if (i >= NN) return;
    int cur = batch[i];
    int prev = (i == 0) ? -1 : batch[i - 1];
    for (int g = prev + 1; g <= cur; ++g) g_gstart[g] = i;
    if (i == NN - 1)
        for (int g = cur + 1; g <= NB; ++g) g_gstart[g] = NN;
}
__global__ void k_deg(const int* __restrict__ dst) {
    int e = blockIdx.x * blockDim.x + threadIdx.x;
    if (e < NE) atomicAdd(&g_deg[dst[e]], 1);
}
__global__ void k_scanA() {
    __shared__ int s[SCAN_BS];
    int i = blockIdx.x * SCAN_BS + threadIdx.x;
    int v = (i < NN) ? g_deg[i] : 0;
    s[threadIdx.x] = v;
    __syncthreads();
#pragma unroll
    for (int off = 1; off < SCAN_BS; off <<= 1) {
        int t = (threadIdx.x >= off) ? s[threadIdx.x - off] : 0;
        __syncthreads();
        s[threadIdx.x] += t;
        __syncthreads();
    }
    if (i < NN) g_rowstart[i] = s[threadIdx.x] - v;
    if (threadIdx.x == SCAN_BS - 1) g_bsum[blockIdx.x] = s[SCAN_BS - 1];
}
// scanC includes the 98-element block-sum prefix (warp 0 of each block)
__global__ void k_scanC() {
    __shared__ int pre[SCAN_NBLK];
    if (threadIdx.x < 32) {
        int lane = threadIdx.x;
        int carry = 0;
        for (int b0 = 0; b0 < SCAN_NBLK; b0 += 32) {
            int i = b0 + lane;
            int orig = (i < SCAN_NBLK) ? g_bsum[i] : 0;
            int v = orig;
#pragma unroll
            for (int o = 1; o < 32; o <<= 1) {
                int t = __shfl_up_sync(0xFFFFFFFFu, v, o);
                if (lane >= o) v += t;
            }
            int total = __shfl_sync(0xFFFFFFFFu, v, 31);
            if (i < SCAN_NBLK) pre[i] = v - orig + carry;
            carry += total;
        }
    }
    __syncthreads();
    int i = blockIdx.x * blockDim.x + threadIdx.x;
    if (i < NN) {
        int r = g_rowstart[i] + pre[i / SCAN_BS];
        g_rowstart[i] = r;
        g_cursor[i] = r;
    }
}
__global__ void k_fill(const int* __restrict__ src, const int* __restrict__ dst) {
    int e = blockIdx.x * blockDim.x + threadIdx.x;
    if (e < NE) {
        int pos = atomicAdd(&g_cursor[dst[e]], 1);
        g_esrc[pos] = src[e];
    }
}

// ---------------- feature prep + gather aggregation ----------------
__global__ void k_concat(const float* __restrict__ h0, const float* __restrict__ coord) {
    int i = blockIdx.x * blockDim.x + threadIdx.x;
    if (i >= NN * F20) return;
    int n = i / F20, j = i - n * F20;
    float v = 0.f;
    if (j < FI)        v = h0[n * FI + j];
    else if (j < F19)  v = coord[n * 3 + (j - FI)];
    g_x19[i] = v;
}

// dense mapping: 5 threads per node, each owns 4 cols
__global__ void k_gather19() {
    int i = blockIdx.x * blockDim.x + threadIdx.x;
    if (i >= NN * 5) return;
    int node = i / 5;
    int c = (i - node * 5) * 4;
    int st = g_rowstart[node], en = g_rowstart[node + 1];
    float4 v = *(const float4*)&g_x19[node * F20 + c];
    for (int e = st; e < en; e++) {
        int s = g_esrc[e];
        float4 u = *(const float4*)&g_x19[s * F20 + c];
        v.x += u.x; v.y += u.y; v.z += u.z; v.w += u.w;
    }
    *(float4*)&g_xa19[node * F20 + c] = v;
}

// warp per node; lane owns cols 4l..4l+3; 4 independent accumulator chains
__global__ void k_gatherH(const float* __restrict__ x, float* __restrict__ xa) {
    int node = blockIdx.x * 8 + (threadIdx.x >> 5);
    if (node >= NN) return;
    int lane = threadIdx.x & 31;
    int st = g_rowstart[node], en = g_rowstart[node + 1];
    float4 v0 = *(const float4*)&x[(size_t)node * HD + lane * 4];
    float4 v1 = make_float4(0.f, 0.f, 0.f, 0.f);
    float4 v2 = make_float4(0.f, 0.f, 0.f, 0.f);
    float4 v3 = make_float4(0.f, 0.f, 0.f, 0.f);
    int e = st;
    for (; e + 3 < en; e += 4) {
        int s0 = g_esrc[e], s1 = g_esrc[e + 1], s2 = g_esrc[e + 2], s3 = g_esrc[e + 3];
        float4 u0 = *(const float4*)&x[(size_t)s0 * HD + lane * 4];
        float4 u1 = *(const float4*)&x[(size_t)s1 * HD + lane * 4];
        float4 u2 = *(const float4*)&x[(size_t)s2 * HD + lane * 4];
        float4 u3 = *(const float4*)&x[(size_t)s3 * HD + lane * 4];
        v0.x += u0.x; v0.y += u0.y; v0.z += u0.z; v0.w += u0.w;
        v1.x += u1.x; v1.y += u1.y; v1.z += u1.z; v1.w += u1.w;
        v2.x += u2.x; v2.y += u2.y; v2.z += u2.z; v2.w += u2.w;
        v3.x += u3.x; v3.y += u3.y; v3.z += u3.z; v3.w += u3.w;
    }
    for (; e < en; e++) {
        int s0 = g_esrc[e];
        float4 u0 = *(const float4*)&x[(size_t)s0 * HD + lane * 4];
        v0.x += u0.x; v0.y += u0.y; v0.z += u0.z; v0.w += u0.w;
    }
    v0.x += v1.x + v2.x + v3.x;
    v0.y += v1.y + v2.y + v3.y;
    v0.z += v1.z + v2.z + v3.z;
    v0.w += v1.w + v2.w + v3.w;
    *(float4*)&xa[(size_t)node * HD + lane * 4] = v0;
}

// ---------------- H-GEMM: k-tile 32, double-buffered, cp.async B ----------------
template <bool TRANS_A, bool STATS, bool ELU>
__global__ void __launch_bounds__(256, 2)
k_gemmH(const float* __restrict__ A, const float* __restrict__ W,
        const float* __restrict__ bias,
        const float* __restrict__ gm, const float* __restrict__ bt,
        float* __restrict__ out) {
    extern __shared__ float sm[];
    float* Asm = sm;            // [2][32*128]
    float* Bsm = sm + 8192;     // [2][32*128]

    const int tid = threadIdx.x;
    const int tx = tid & 15;
    const int ty = tid >> 4;
    const int m0 = blockIdx.x * 128;
    const int ar = tid >> 1;
    const int aq0 = 4 * (tid & 1);

    ull acc[8][4];
#pragma unroll
    for (int r = 0; r < 8; r++)
#pragma unroll
        for (int c = 0; c < 4; c++) acc[r][c] = 0ull;

    float4 pa[4];
#pragma unroll
    for (int p = 0; p < 4; p++) {
        int grow = m0 + ar;
        pa[p] = (grow < NN) ? *(const float4*)&A[(size_t)grow * HD + (aq0 + p) * 4]
                            : make_float4(0.f, 0.f, 0.f, 0.f);
    }
#pragma unroll
    for (int p = 0; p < 4; p++) {
        int idx = p * 256 + tid;
        int kk = idx >> 5, n4 = idx & 31;
        cp16(smem_u32(&Bsm[kk * 128 + n4 * 4]), &W[(size_t)kk * HD + n4 * 4]);
    }
    asm volatile("cp.async.commit_group;" ::: "memory");
#pragma unroll
    for (int p = 0; p < 4; p++) {
        int q = aq0 + p;
        float4 v = pa[p];
        if (TRANS_A) {
            float4 ca = *(const float4*)&g_coef[q * 4];
            float4 cb = *(const float4*)&g_coef[128 + q * 4];
            v.x = fmaxf(fmaf(ca.x, v.x, cb.x), 0.f);
            v.y = fmaxf(fmaf(ca.y, v.y, cb.y), 0.f);
            v.z = fmaxf(fmaf(ca.z, v.z, cb.z), 0.f);
            v.w = fmaxf(fmaf(ca.w, v.w, cb.w), 0.f);
        }
        Asm[(q * 4 + 0) * 128 + ar] = v.x;
        Asm[(q * 4 + 1) * 128 + ar] = v.y;
        Asm[(q * 4 + 2) * 128 + ar] = v.z;
        Asm[(q * 4 + 3) * 128 + ar] = v.w;
    }
    asm volatile("cp.async.wait_group 0;" ::: "memory");
    __syncthreads();

#pragma unroll
    for (int kt = 0; kt < 4; kt++) {
        const float* Ac = Asm + (kt & 1) * 4096;
        const float* Bc = Bsm + (kt & 1) * 4096;
        if (kt < 3) {
            const int k0n = (kt + 1) * 32;
            float* Bn = Bsm + ((kt + 1) & 1) * 4096;
#pragma unroll
            for (int p = 0; p < 4; p++) {
                int idx = p * 256 + tid;
                int kk = idx >> 5, n4 = idx & 31;
                cp16(smem_u32(&Bn[kk * 128 + n4 * 4]), &W[(size_t)(k0n + kk) * HD + n4 * 4]);
            }
            asm volatile("cp.async.commit_group;" ::: "memory");
#pragma unroll
            for (int p = 0; p < 4; p++) {
                int grow = m0 + ar;
                pa[p] = (grow < NN)
                    ? *(const float4*)&A[(size_t)grow * HD + k0n + (aq0 + p) * 4]
                    : make_float4(0.f, 0.f, 0.f, 0.f);
            }
        }
#pragma unroll
        for (int k = 0; k < 32; k++) {
            float4 a0 = *(const float4*)&Ac[k * 128 + ty * 8];
            float4 a1 = *(const float4*)&Ac[k * 128 + ty * 8 + 4];
            float4 b0 = *(const float4*)&Bc[k * 128 + tx * 8];
            float4 b1 = *(const float4*)&Bc[k * 128 + tx * 8 + 4];
            ull bp0 = pk2(b0.x, b0.y), bp1 = pk2(b0.z, b0.w);
            ull bp2 = pk2(b1.x, b1.y), bp3 = pk2(b1.z, b1.w);
            float arr[8] = {a0.x, a0.y, a0.z, a0.w, a1.x, a1.y, a1.z, a1.w};
#pragma unroll
            for (int r = 0; r < 8; r++) {
                ull ap = dup2(arr[r]);
                ffma2(acc[r][0], ap, bp0);
                ffma2(acc[r][1], ap, bp1);
                ffma2(acc[r][2], ap, bp2);
                ffma2(acc[r][3], ap, bp3);
            }
        }
        if (kt < 3) {
            const int k0n = (kt + 1) * 32;
            float* An = Asm + ((kt + 1) & 1) * 4096;
#pragma unroll
            for (int p = 0; p < 4; p++) {
                int q = aq0 + p;
                float4 v = pa[p];
                if (TRANS_A) {
                    float4 ca = *(const float4*)&g_coef[k0n + q * 4];
                    float4 cb = *(const float4*)&g_coef[128 + k0n + q * 4];
                    v.x = fmaxf(fmaf(ca.x, v.x, cb.x), 0.f);
                    v.y = fmaxf(fmaf(ca.y, v.y, cb.y), 0.f);
                    v.z = fmaxf(fmaf(ca.z, v.z, cb.z), 0.f);
                    v.w = fmaxf(fmaf(ca.w, v.w, cb.w), 0.f);
                }
                An[(q * 4 + 0) * 128 + ar] = v.x;
                An[(q * 4 + 1) * 128 + ar] = v.y;
                An[(q * 4 + 2) * 128 + ar] = v.z;
                An[(q * 4 + 3) * 128 + ar] = v.w;
            }
            asm volatile("cp.async.wait_group 0;" ::: "memory");
        }
        __syncthreads();
    }

    // ---- epilogue ----
    float4 bb0 = *(const float4*)&bias[tx * 8];
    float4 bb1 = *(const float4*)&bias[tx * 8 + 4];
    float bv[8] = {bb0.x, bb0.y, bb0.z, bb0.w, bb1.x, bb1.y, bb1.z, bb1.w};

    float cS[8], cQ[8];
    if (STATS) {
#pragma unroll
        for (int c = 0; c < 8; c++) { cS[c] = 0.f; cQ[c] = 0.f; }
    }
#pragma unroll
    for (int r = 0; r < 8; r++) {
        int grow = m0 + ty * 8 + r;
        if (grow < NN) {
            float2 p0 = upk(acc[r][0]), p1 = upk(acc[r][1]);
            float2 p2 = upk(acc[r][2]), p3 = upk(acc[r][3]);
            float v[8] = {p0.x, p0.y, p1.x, p1.y, p2.x, p2.y, p3.x, p3.y};
#pragma unroll
            for (int c = 0; c < 8; c++) {
                v[c] += bv[c];
                if (STATS) { cS[c] += v[c]; cQ[c] += v[c] * v[c]; }
                if (ELU) v[c] = elu01(v[c]);
            }
            *(float4*)&out[(size_t)grow * HD + tx * 8]     = make_float4(v[0], v[1], v[2], v[3]);
            *(float4*)&out[(size_t)grow * HD + tx * 8 + 4] = make_float4(v[4], v[5], v[6], v[7]);
        }
    }
    if (STATS)
        stats_epilogue<GB_H>(Asm, cS, cQ, tid, tx, ty, gm, bt);
}

// ---------------- FFMA2 GEMM (layer-0, K=19) with stats + coef ----------------
__device__ __forceinline__ void ld_tiles19(const float* __restrict__ A,
                                           const float* __restrict__ W,
                                           int m0, int k0, int tid,
                                           float4* pa, float4* pw) {
#pragma unroll
    for (int p = 0; p < 2; p++) {
        int idx = tid * 2 + p;
        int r = idx >> 2, kq = idx & 3;
        int gk = k0 + kq * 4, grow = m0 + r;
        float4 v = make_float4(0.f, 0.f, 0.f, 0.f);
        if (grow < NN && gk < F19) v = *(const float4*)&A[(size_t)grow * F20 + gk];
        pa[p] = v;
        int kk = idx >> 5, n4 = idx & 31;
        float4 w = make_float4(0.f, 0.f, 0.f, 0.f);
        if (k0 + kk < F19) w = *(const float4*)&W[(size_t)(k0 + kk) * HD + n4 * 4];
        pw[p] = w;
    }
}
__device__ __forceinline__ void st_tiles19(float* __restrict__ As, float* __restrict__ Bs,
                                           int tid, const float4* pa, const float4* pw) {
#pragma unroll
    for (int p = 0; p < 2; p++) {
        int idx = tid * 2 + p;
        int r = idx >> 2, kq = idx & 3;
        float4 v = pa[p];
        As[(kq * 4 + 0) * 128 + r] = v.x;
        As[(kq * 4 + 1) * 128 + r] = v.y;
        As[(kq * 4 + 2) * 128 + r] = v.z;
        As[(kq * 4 + 3) * 128 + r] = v.w;
        int kk = idx >> 5, n4 = idx & 31;
        *(float4*)&Bs[kk * 128 + n4 * 4] = pw[p];
    }
}

__global__ void __launch_bounds__(256, 2)
k_gemm19(const float* __restrict__ A, const float* __restrict__ W,
         const float* __restrict__ bias,
         const float* __restrict__ gm, const float* __restrict__ bt,
         float* __restrict__ out) {
    __shared__ float As[2][16 * 128];
    __shared__ float Bs[2][16 * 128];
    const int tid = threadIdx.x;
    const int tx = tid & 15;
    const int ty = tid >> 4;
    const int m0 = blockIdx.x * 128;

    ull acc[8][4];
#pragma unroll
    for (int r = 0; r < 8; r++)
#pragma unroll
        for (int c = 0; c < 4; c++) acc[r][c] = 0ull;

    float4 pa[2], pw[2];
    ld_tiles19(A, W, m0, 0, tid, pa, pw);
    st_tiles19(As[0], Bs[0], tid, pa, pw);
    __syncthreads();

#pragma unroll
    for (int kt = 0; kt < 2; kt++) {
        const float* Ac = As[kt & 1];
        const float* Bc = Bs[kt & 1];
        if (kt == 0) ld_tiles19(A, W, m0, 16, tid, pa, pw);
#pragma unroll
        for (int k = 0; k < 16; k++) {
            float4 a0 = *(const float4*)&Ac[k * 128 + ty * 8];
            float4 a1 = *(const float4*)&Ac[k * 128 + ty * 8 + 4];
            float4 b0 = *(const float4*)&Bc[k * 128 + tx * 8];
            float4 b1 = *(const float4*)&Bc[k * 128 + tx * 8 + 4];
            ull bp0 = pk2(b0.x, b0.y), bp1 = pk2(b0.z, b0.w);
            ull bp2 = pk2(b1.x, b1.y), bp3 = pk2(b1.z, b1.w);
            float arr[8] = {a0.x, a0.y, a0.z, a0.w, a1.x, a1.y, a1.z, a1.w};
#pragma unroll
            for (int r = 0; r < 8; r++) {
                ull ap = dup2(arr[r]);
                ffma2(acc[r][0], ap, bp0);
                ffma2(acc[r][1], ap, bp1);
                ffma2(acc[r][2], ap, bp2);
                ffma2(acc[r][3], ap, bp3);
            }
        }
        if (kt == 0) st_tiles19(As[1], Bs[1], tid, pa, pw);
        __syncthreads();
    }

    float4 bb0 = *(const float4*)&bias[tx * 8];
    float4 bb1 = *(const float4*)&bias[tx * 8 + 4];
    float bv[8] = {bb0.x, bb0.y, bb0.z, bb0.w, bb1.x, bb1.y, bb1.z, bb1.w};
    float cS[8], cQ[8];
#pragma unroll
    for (int c = 0; c < 8; c++) { cS[c] = 0.f; cQ[c] = 0.f; }
#pragma unroll
    for (int r = 0; r < 8; r++) {
        int grow = m0 + ty * 8 + r;
        if (grow < NN) {
            float2 p0 = upk(acc[r][0]), p1 = upk(acc[r][1]);
            float2 p2 = upk(acc[r][2]), p3 = upk(acc[r][3]);
            float v[8] = {p0.x, p0.y, p1.x, p1.y, p2.x, p2.y, p3.x, p3.y};
#pragma unroll
            for (int c = 0; c < 8; c++) {
                v[c] += bv[c];
                cS[c] += v[c]; cQ[c] += v[c] * v[c];
            }
            *(float4*)&out[(size_t)grow * HD + tx * 8]     = make_float4(v[0], v[1], v[2], v[3]);
            *(float4*)&out[(size_t)grow * HD + tx * 8 + 4] = make_float4(v[4], v[5], v[6], v[7]);
        }
    }
    stats_epilogue<GB_H>(As[0], cS, cQ, tid, tx, ty, gm, bt);
}

// ---------------- pooling / classifier ----------------
__global__ void k_pool(const float* __restrict__ x) {
    __shared__ float ps[4][128];
    __shared__ float pm[4][128];
    int b = blockIdx.x;
    int rg = threadIdx.x >> 7, c = threadIdx.x & 127;
    int st = g_gstart[b], en = g_gstart[b + 1];
    float s = 0.f, m = -INFINITY;
    for (int r = st + rg; r < en; r += 4) {
        float v = x[(size_t)r * HD + c];
        s += v;
        m = fmaxf(m, v);
    }
    ps[rg][c] = s;
    pm[rg][c] = m;
    __syncthreads();
    if (rg == 0) {
        float ss = ps[0][c] + ps[1][c] + ps[2][c] + ps[3][c];
        float mm = fmaxf(fmaxf(pm[0][c], pm[1][c]), fmaxf(pm[2][c], pm[3][c]));
        int cnt = en - st;
        g_pooled[b * 256 + c] = ss / (float)(cnt > 0 ? cnt : 1);
        g_pooled[b * 256 + 128 + c] = mm;
    }
}

__global__ void k_cls(const float* __restrict__ g0,
                      const float* __restrict__ cw1, const float* __restrict__ cb1,
                      const float* __restrict__ cgm, const float* __restrict__ cbt,
                      const float* __restrict__ cw2, const float* __restrict__ cb2,
                      float* __restrict__ out) {
    __shared__ float zrow[8][264];
    __shared__ float h1[64][128];
    __shared__ float lg[64][2];
    int c = threadIdx.x;  // <<<1,128>>>

    for (int r0 = 0; r0 < 64; r0 += 8) {
        for (int idx = c; idx < 8 * 264; idx += 128) {
            int rr = idx / 264, k = idx - rr * 264;
            int r = r0 + rr;
            zrow[rr][k] = (k < 256) ? g_pooled[r * 256 + k] : g0[r * GF + (k - 256)];
        }
        __syncthreads();
        float acc[8];
#pragma unroll
        for (int rr = 0; rr < 8; rr++) acc[rr] = 0.f;
        for (int k = 0; k < 264; ++k) {
            float w = cw1[k * HD + c];
#pragma unroll
            for (int rr = 0; rr < 8; rr++) acc[rr] += zrow[rr][k] * w;
        }
        float bias = cb1[c];
#pragma unroll
        for (int rr = 0; rr < 8; rr++) h1[r0 + rr][c] = elu01(acc[rr] + bias);
        __syncthreads();
    }

    float s = 0.f, sq = 0.f;
    for (int r = 0; r < 64; r++) {
        float v = h1[r][c];
        s += v;
        sq += v * v;
    }
    float mean = s * (1.f / 64.f);
    float var = sq * (1.f / 64.f) - mean * mean;
    float a = cgm[c] * rsqrtf(var + BN_EPS);
    float bb = cbt[c] - mean * a;
    for (int r = 0; r < 64; r++) h1[r][c] = h1[r][c] * a + bb;
    __syncthreads();

    {
        int r = c >> 1, cls = c & 1;
        float l = cb2[cls];
        for (int k = 0; k < 128; k++) l += h1[r][k] * cw2[k * 2 + cls];
        lg[r][cls] = l;
    }
    __syncthreads();
    {
        int r = c >> 1, cls = c & 1;
        float l0 = lg[r][0], l1 = lg[r][1];
        float mx = fmaxf(l0, l1);
        float e0 = expf(l0 - mx), e1 = expf(l1 - mx);
        out[r * 2 + cls] = ((cls == 0) ? e0 : e1) / (e0 + e1);
    }
}

// ---------------- launch ----------------
extern "C" void kernel_launch(void* const* d_in, const int* in_sizes, int n_in,
                              void* d_out, int out_size) {
    const float* h0     = (const float*)d_in[0];
    const float* coord0 = (const float*)d_in[1];
    const float* g0     = (const float*)d_in[2];
    const int*   eidx   = (const int*)  d_in[3];
    const int*   batch  = (const int*)  d_in[4];
    const float* w1_0 = (const float*)d_in[5];
    const float* b1_0 = (const float*)d_in[6];
    const float* gm_0 = (const float*)d_in[7];
    const float* bt_0 = (const float*)d_in[8];
    const float* w2_0 = (const float*)d_in[9];
    const float* b2_0 = (const float*)d_in[10];
    const float* w1_r = (const float*)d_in[11];
    const float* b1_r = (const float*)d_in[12];
    const float* gm_r = (const float*)d_in[13];
    const float* bt_r = (const float*)d_in[14];
    const float* w2_r = (const float*)d_in[15];
    const float* b2_r = (const float*)d_in[16];
    const float* cw1  = (const float*)d_in[17];
    const float* cb1  = (const float*)d_in[18];
    const float* cgm  = (const float*)d_in[19];
    const float* cbt  = (const float*)d_in[20];
    const float* cw2  = (const float*)d_in[21];
    const float* cb2  = (const float*)d_in[22];

    const int* src = eidx;
    const int* dst = eidx + NE;

    float *xa19, *h, *xagg, *xA, *xB;
    cudaGetSymbolAddress((void**)&xa19, g_xa19);
    cudaGetSymbolAddress((void**)&h,    g_h);
    cudaGetSymbolAddress((void**)&xagg, g_xagg);
    cudaGetSymbolAddress((void**)&xA,   g_xA);
    cudaGetSymbolAddress((void**)&xB,   g_xB);

    cudaFuncSetAttribute(k_gemmH<true, false, true>,
                         cudaFuncAttributeMaxDynamicSharedMemorySize, GH_SMEM);
    cudaFuncSetAttribute(k_gemmH<false, true, false>,
                         cudaFuncAttributeMaxDynamicSharedMemorySize, GH_SMEM);

    // ---- CSR build (+ zeroing fused into k_bounds) ----
    k_bounds<<<(NN + 255) / 256, 256>>>(batch);
    k_deg<<<(NE + 255) / 256, 256>>>(dst);
    k_scanA<<<SCAN_NBLK, SCAN_BS>>>();
    k_scanC<<<(NN + 255) / 256, 256>>>();
    k_fill<<<(NE + 255) / 256, 256>>>(src, dst);

    // ---- layer 0 ----
    k_concat<<<(NN * F20 + 255) / 256, 256>>>(h0, coord0);
    k_gather19<<<(NN * 5 + 255) / 256, 256>>>();
    k_gemm19<<<GB_H, 256>>>(xa19, w1_0, b1_0, gm_0, bt_0, h);
    k_gemmH<true, false, true><<<GB_H, 256, GH_SMEM>>>(h, w2_0, b2_0, nullptr, nullptr, xA);

    // ---- layers 1..2 ----
    for (int i = 0; i < 2; i++) {
        const float* xin = (i == 0) ? xA : xB;
        float* xout      = (i == 0) ? xB : xA;
        k_gatherH<<<(NN + 7) / 8, 256>>>(xin, xagg);
        k_gemmH<false, true, false><<<GB_H, 256, GH_SMEM>>>(
            xagg, w1_r + i * HD * HD, b1_r + i * HD, gm_r + i * HD, bt_r + i * HD, h);
        k_gemmH<true, false, true><<<GB_H, 256, GH_SMEM>>>(
            h, w2_r + i * HD * HD, b2_r + i * HD, nullptr, nullptr, xout);
    }

    // ---- pooling + classifier ----
    k_pool<<<NB, 512>>>(xA);
    k_cls<<<1, 128>>>(g0, cw1, cb1, cgm, cbt, cw2, cb2, (float*)d_out);
}

// round 17
// speedup vs baseline: 1.0553x; 1.0340x over previous
#include <cuda_runtime.h>
#include <math.h>
#include <stdint.h>

#define NN 100000
#define NE 1600000
#define NB 64
#define FI 16
#define HD 128
#define GF 8
#define F19 19
#define F20 20
#define BN_EPS 1e-5f
#define SCAN_BS 1024
#define SCAN_NBLK ((NN + SCAN_BS - 1) / SCAN_BS)   // 98
#define GH_SMEM 65536                               // k_gemmH dynamic smem
#define GB_H ((NN + 127) / 128)                     // 782

typedef unsigned long long ull;

// ---------------- scratch (device globals: allocation-free) ----------------
__device__ float g_x19 [NN * F20];
__device__ float g_xa19[NN * F20];
__device__ float g_h   [NN * HD];
__device__ float g_xagg[NN * HD];
__device__ float g_xA  [NN * HD];
__device__ float g_xB  [NN * HD];
__device__ float g_stats[2 * HD];
__device__ float g_coef [2 * HD];
__device__ int   g_ctr;
__device__ int   g_gstart[NB + 1];
__device__ float g_pooled[NB * 2 * HD];
// CSR scratch
__device__ int g_deg[NN];
__device__ int g_rowstart[NN + 1];
__device__ int g_cursor[NN];
__device__ int g_esrc[NE];
__device__ int g_bsum[SCAN_NBLK];

// ---------------- helpers ----------------
__device__ __forceinline__ float elu01(float v) {
    return v > 0.f ? v : 0.1f * expm1f(v);
}
__device__ __forceinline__ void ffma2(ull& d, ull a, ull b) {
    asm("fma.rn.f32x2 %0, %1, %2, %0;" : "+l"(d) : "l"(a), "l"(b));
}
__device__ __forceinline__ ull dup2(float a) {
    ull r; asm("mov.b64 %0, {%1, %1};" : "=l"(r) : "f"(a)); return r;
}
__device__ __forceinline__ ull pk2(float x, float y) {
    ull r; asm("mov.b64 %0, {%1, %2};" : "=l"(r) : "f"(x), "f"(y)); return r;
}
__device__ __forceinline__ float2 upk(ull v) {
    float2 f; asm("mov.b64 {%0, %1}, %2;" : "=f"(f.x), "=f"(f.y) : "l"(v)); return f;
}
__device__ __forceinline__ uint32_t smem_u32(const void* p) {
    return (uint32_t)__cvta_generic_to_shared(p);
}
__device__ __forceinline__ void cp16(uint32_t dst, const void* src) {
    asm volatile("cp.async.ca.shared.global [%0], [%1], 16;" :: "r"(dst), "l"(src) : "memory");
}

// stats -> BN coef epilogue; scr = 16*128 float smem scratch
template <int GRID>
__device__ __forceinline__ void stats_epilogue(
    float* scr, const float* cS, const float* cQ, int tid, int tx, int ty,
    const float* gm, const float* bt) {
    __syncthreads();
#pragma unroll
    for (int c = 0; c < 8; c++) scr[ty * 128 + tx * 8 + c] = cS[c];
    __syncthreads();
    if (tid < 128) {
        float s = 0.f;
#pragma unroll
        for (int j = 0; j < 16; j++) s += scr[j * 128 + tid];
        atomicAdd(&g_stats[tid], s);
    }
    __syncthreads();
#pragma unroll
    for (int c = 0; c < 8; c++) scr[ty * 128 + tx * 8 + c] = cQ[c];
    __syncthreads();
    if (tid < 128) {
        float s = 0.f;
#pragma unroll
        for (int j = 0; j < 16; j++) s += scr[j * 128 + tid];
        atomicAdd(&g_stats[128 + tid], s);
    }
    __shared__ int s_last;
    __threadfence();
    __syncthreads();
    if (tid == 0) s_last = (atomicAdd(&g_ctr, 1) == GRID - 1) ? 1 : 0;
    __syncthreads();
    if (s_last) {
        __threadfence();
        if (tid < 128) {
            float mean = g_stats[tid] * (1.f / NN);
            float var = g_stats[128 + tid] * (1.f / NN) - mean * mean;
            float a = gm[tid] * rsqrtf(var + BN_EPS);
            g_coef[tid] = a;
            g_coef[128 + tid] = bt[tid] - mean * a;
            g_stats[tid] = 0.f;
            g_stats[128 + tid] = 0.f;
        }
        __threadfence();
        if (tid == 0) g_ctr = 0;
    }
}

// ---------------- CSR build ----------------
__global__ void k_bounds(const int* __restrict__ batch) {
    int i = blockIdx.x * blockDim.x + threadIdx.x;
    if (i < NN) g_deg[i] = 0;
    if (i < 256) g_stats[i] = 0.f;
    if (i == 0) { g_ctr = 0; g_rowstart[NN] = NE; }
    if (i >= NN) return;
    int cur = batch[i];
    int prev = (i == 0) ? -1 : batch[i - 1];
    for (int g = prev + 1; g <= cur; ++g) g_gstart[g] = i;
    if (i == NN - 1)
        for (int g = cur + 1; g <= NB; ++g) g_gstart[g] = NN;
}
__global__ void k_deg(const int* __restrict__ dst) {
    int e = blockIdx.x * blockDim.x + threadIdx.x;
    if (e < NE) atomicAdd(&g_deg[dst[e]], 1);
}
__global__ void k_scanA() {
    __shared__ int s[SCAN_BS];
    int i = blockIdx.x * SCAN_BS + threadIdx.x;
    int v = (i < NN) ? g_deg[i] : 0;
    s[threadIdx.x] = v;
    __syncthreads();
#pragma unroll
    for (int off = 1; off < SCAN_BS; off <<= 1) {
        int t = (threadIdx.x >= off) ? s[threadIdx.x - off] : 0;
        __syncthreads();
        s[threadIdx.x] += t;
        __syncthreads();
    }
    if (i < NN) g_rowstart[i] = s[threadIdx.x] - v;
    if (threadIdx.x == SCAN_BS - 1) g_bsum[blockIdx.x] = s[SCAN_BS - 1];
}
// scanC includes the 98-element block-sum prefix (warp 0 of each block)
__global__ void k_scanC() {
    __shared__ int pre[SCAN_NBLK];
    if (threadIdx.x < 32) {
        int lane = threadIdx.x;
        int carry = 0;
        for (int b0 = 0; b0 < SCAN_NBLK; b0 += 32) {
            int i = b0 + lane;
            int orig = (i < SCAN_NBLK) ? g_bsum[i] : 0;
            int v = orig;
#pragma unroll
            for (int o = 1; o < 32; o <<= 1) {
                int t = __shfl_up_sync(0xFFFFFFFFu, v, o);
                if (lane >= o) v += t;
            }
            int total = __shfl_sync(0xFFFFFFFFu, v, 31);
            if (i < SCAN_NBLK) pre[i] = v - orig + carry;
            carry += total;
        }
    }
    __syncthreads();
    int i = blockIdx.x * blockDim.x + threadIdx.x;
    if (i < NN) {
        int r = g_rowstart[i] + pre[i / SCAN_BS];
        g_rowstart[i] = r;
        g_cursor[i] = r;
    }
}
__global__ void k_fill(const int* __restrict__ src, const int* __restrict__ dst) {
    int e = blockIdx.x * blockDim.x + threadIdx.x;
    if (e < NE) {
        int pos = atomicAdd(&g_cursor[dst[e]], 1);
        g_esrc[pos] = src[e];
    }
}

// ---------------- feature prep + gather aggregation ----------------
__global__ void k_concat(const float* __restrict__ h0, const float* __restrict__ coord) {
    int i = blockIdx.x * blockDim.x + threadIdx.x;
    if (i >= NN * F20) return;
    int n = i / F20, j = i - n * F20;
    float v = 0.f;
    if (j < FI)        v = h0[n * FI + j];
    else if (j < F19)  v = coord[n * 3 + (j - FI)];
    g_x19[i] = v;
}

// dense mapping: 5 threads per node, each owns 4 cols
__global__ void k_gather19() {
    int i = blockIdx.x * blockDim.x + threadIdx.x;
    if (i >= NN * 5) return;
    int node = i / 5;
    int c = (i - node * 5) * 4;
    int st = g_rowstart[node], en = g_rowstart[node + 1];
    float4 v = *(const float4*)&g_x19[node * F20 + c];
    for (int e = st; e < en; e++) {
        int s = g_esrc[e];
        float4 u = *(const float4*)&g_x19[s * F20 + c];
        v.x += u.x; v.y += u.y; v.z += u.z; v.w += u.w;
    }
    *(float4*)&g_xa19[node * F20 + c] = v;
}

// warp per node; lane owns cols 4l..4l+3; 2 accumulator chains (R11-proven)
__global__ void k_gatherH(const float* __restrict__ x, float* __restrict__ xa) {
    int node = blockIdx.x * 8 + (threadIdx.x >> 5);
    if (node >= NN) return;
    int lane = threadIdx.x & 31;
    int st = g_rowstart[node], en = g_rowstart[node + 1];
    float4 v0 = *(const float4*)&x[(size_t)node * HD + lane * 4];
    float4 v1 = make_float4(0.f, 0.f, 0.f, 0.f);
    int e = st;
    for (; e + 1 < en; e += 2) {
        int s0 = g_esrc[e], s1 = g_esrc[e + 1];
        float4 u0 = *(const float4*)&x[(size_t)s0 * HD + lane * 4];
        float4 u1 = *(const float4*)&x[(size_t)s1 * HD + lane * 4];
        v0.x += u0.x; v0.y += u0.y; v0.z += u0.z; v0.w += u0.w;
        v1.x += u1.x; v1.y += u1.y; v1.z += u1.z; v1.w += u1.w;
    }
    if (e < en) {
        int s0 = g_esrc[e];
        float4 u0 = *(const float4*)&x[(size_t)s0 * HD + lane * 4];
        v0.x += u0.x; v0.y += u0.y; v0.z += u0.z; v0.w += u0.w;
    }
    v0.x += v1.x; v0.y += v1.y; v0.z += v1.z; v0.w += v1.w;
    *(float4*)&xa[(size_t)node * HD + lane * 4] = v0;
}

// ---------------- H-GEMM: k-tile 32, double-buffered, cp.async B ----------------
template <bool TRANS_A, bool STATS, bool ELU>
__global__ void __launch_bounds__(256, 2)
k_gemmH(const float* __restrict__ A, const float* __restrict__ W,
        const float* __restrict__ bias,
        const float* __restrict__ gm, const float* __restrict__ bt,
        float* __restrict__ out) {
    extern __shared__ float sm[];
    float* Asm = sm;            // [2][32*128]
    float* Bsm = sm + 8192;     // [2][32*128]

    const int tid = threadIdx.x;
    const int tx = tid & 15;
    const int ty = tid >> 4;
    const int m0 = blockIdx.x * 128;
    const int ar = tid >> 1;
    const int aq0 = 4 * (tid & 1);

    ull acc[8][4];
#pragma unroll
    for (int r = 0; r < 8; r++)
#pragma unroll
        for (int c = 0; c < 4; c++) acc[r][c] = 0ull;

    float4 pa[4];
#pragma unroll
    for (int p = 0; p < 4; p++) {
        int grow = m0 + ar;
        pa[p] = (grow < NN) ? *(const float4*)&A[(size_t)grow * HD + (aq0 + p) * 4]
                            : make_float4(0.f, 0.f, 0.f, 0.f);
    }
#pragma unroll
    for (int p = 0; p < 4; p++) {
        int idx = p * 256 + tid;
        int kk = idx >> 5, n4 = idx & 31;
        cp16(smem_u32(&Bsm[kk * 128 + n4 * 4]), &W[(size_t)kk * HD + n4 * 4]);
    }
    asm volatile("cp.async.commit_group;" ::: "memory");
#pragma unroll
    for (int p = 0; p < 4; p++) {
        int q = aq0 + p;
        float4 v = pa[p];
        if (TRANS_A) {
            float4 ca = *(const float4*)&g_coef[q * 4];
            float4 cb = *(const float4*)&g_coef[128 + q * 4];
            v.x = fmaxf(fmaf(ca.x, v.x, cb.x), 0.f);
            v.y = fmaxf(fmaf(ca.y, v.y, cb.y), 0.f);
            v.z = fmaxf(fmaf(ca.z, v.z, cb.z), 0.f);
            v.w = fmaxf(fmaf(ca.w, v.w, cb.w), 0.f);
        }
        Asm[(q * 4 + 0) * 128 + ar] = v.x;
        Asm[(q * 4 + 1) * 128 + ar] = v.y;
        Asm[(q * 4 + 2) * 128 + ar] = v.z;
        Asm[(q * 4 + 3) * 128 + ar] = v.w;
    }
    asm volatile("cp.async.wait_group 0;" ::: "memory");
    __syncthreads();

#pragma unroll
    for (int kt = 0; kt < 4; kt++) {
        const float* Ac = Asm + (kt & 1) * 4096;
        const float* Bc = Bsm + (kt & 1) * 4096;
        if (kt < 3) {
            const int k0n = (kt + 1) * 32;
            float* Bn = Bsm + ((kt + 1) & 1) * 4096;
#pragma unroll
            for (int p = 0; p < 4; p++) {
                int idx = p * 256 + tid;
                int kk = idx >> 5, n4 = idx & 31;
                cp16(smem_u32(&Bn[kk * 128 + n4 * 4]), &W[(size_t)(k0n + kk) * HD + n4 * 4]);
            }
            asm volatile("cp.async.commit_group;" ::: "memory");
#pragma unroll
            for (int p = 0; p < 4; p++) {
                int grow = m0 + ar;
                pa[p] = (grow < NN)
                    ? *(const float4*)&A[(size_t)grow * HD + k0n + (aq0 + p) * 4]
                    : make_float4(0.f, 0.f, 0.f, 0.f);
            }
        }
#pragma unroll
        for (int k = 0; k < 32; k++) {
            float4 a0 = *(const float4*)&Ac[k * 128 + ty * 8];
            float4 a1 = *(const float4*)&Ac[k * 128 + ty * 8 + 4];
            float4 b0 = *(const float4*)&Bc[k * 128 + tx * 8];
            float4 b1 = *(const float4*)&Bc[k * 128 + tx * 8 + 4];
            ull bp0 = pk2(b0.x, b0.y), bp1 = pk2(b0.z, b0.w);
            ull bp2 = pk2(b1.x, b1.y), bp3 = pk2(b1.z, b1.w);
            float arr[8] = {a0.x, a0.y, a0.z, a0.w, a1.x, a1.y, a1.z, a1.w};
#pragma unroll
            for (int r = 0; r < 8; r++) {
                ull ap = dup2(arr[r]);
                ffma2(acc[r][0], ap, bp0);
                ffma2(acc[r][1], ap, bp1);
                ffma2(acc[r][2], ap, bp2);
                ffma2(acc[r][3], ap, bp3);
            }
        }
        if (kt < 3) {
            const int k0n = (kt + 1) * 32;
            float* An = Asm + ((kt + 1) & 1) * 4096;
#pragma unroll
            for (int p = 0; p < 4; p++) {
                int q = aq0 + p;
                float4 v = pa[p];
                if (TRANS_A) {
                    float4 ca = *(const float4*)&g_coef[k0n + q * 4];
                    float4 cb = *(const float4*)&g_coef[128 + k0n + q * 4];
                    v.x = fmaxf(fmaf(ca.x, v.x, cb.x), 0.f);
                    v.y = fmaxf(fmaf(ca.y, v.y, cb.y), 0.f);
                    v.z = fmaxf(fmaf(ca.z, v.z, cb.z), 0.f);
                    v.w = fmaxf(fmaf(ca.w, v.w, cb.w), 0.f);
                }
                An[(q * 4 + 0) * 128 + ar] = v.x;
                An[(q * 4 + 1) * 128 + ar] = v.y;
                An[(q * 4 + 2) * 128 + ar] = v.z;
                An[(q * 4 + 3) * 128 + ar] = v.w;
            }
            asm volatile("cp.async.wait_group 0;" ::: "memory");
        }
        __syncthreads();
    }

    // ---- epilogue ----
    float4 bb0 = *(const float4*)&bias[tx * 8];
    float4 bb1 = *(const float4*)&bias[tx * 8 + 4];
    float bv[8] = {bb0.x, bb0.y, bb0.z, bb0.w, bb1.x, bb1.y, bb1.z, bb1.w};

    float cS[8], cQ[8];
    if (STATS) {
#pragma unroll
        for (int c = 0; c < 8; c++) { cS[c] = 0.f; cQ[c] = 0.f; }
    }
#pragma unroll
    for (int r = 0; r < 8; r++) {
        int grow = m0 + ty * 8 + r;
        if (grow < NN) {
            float2 p0 = upk(acc[r][0]), p1 = upk(acc[r][1]);
            float2 p2 = upk(acc[r][2]), p3 = upk(acc[r][3]);
            float v[8] = {p0.x, p0.y, p1.x, p1.y, p2.x, p2.y, p3.x, p3.y};
#pragma unroll
            for (int c = 0; c < 8; c++) {
                v[c] += bv[c];
                if (STATS) { cS[c] += v[c]; cQ[c] += v[c] * v[c]; }
                if (ELU) v[c] = elu01(v[c]);
            }
            *(float4*)&out[(size_t)grow * HD + tx * 8]     = make_float4(v[0], v[1], v[2], v[3]);
            *(float4*)&out[(size_t)grow * HD + tx * 8 + 4] = make_float4(v[4], v[5], v[6], v[7]);
        }
    }
    if (STATS)
        stats_epilogue<GB_H>(Asm, cS, cQ, tid, tx, ty, gm, bt);
}

// ---------------- FFMA2 GEMM (layer-0, K=19) with stats + coef ----------------
__device__ __forceinline__ void ld_tiles19(const float* __restrict__ A,
                                           const float* __restrict__ W,
                                           int m0, int k0, int tid,
                                           float4* pa, float4* pw) {
#pragma unroll
    for (int p = 0; p < 2; p++) {
        int idx = tid * 2 + p;
        int r = idx >> 2, kq = idx & 3;
        int gk = k0 + kq * 4, grow = m0 + r;
        float4 v = make_float4(0.f, 0.f, 0.f, 0.f);
        if (grow < NN && gk < F19) v = *(const float4*)&A[(size_t)grow * F20 + gk];
        pa[p] = v;
        int kk = idx >> 5, n4 = idx & 31;
        float4 w = make_float4(0.f, 0.f, 0.f, 0.f);
        if (k0 + kk < F19) w = *(const float4*)&W[(size_t)(k0 + kk) * HD + n4 * 4];
        pw[p] = w;
    }
}
__device__ __forceinline__ void st_tiles19(float* __restrict__ As, float* __restrict__ Bs,
                                           int tid, const float4* pa, const float4* pw) {
#pragma unroll
    for (int p = 0; p < 2; p++) {
        int idx = tid * 2 + p;
        int r = idx >> 2, kq = idx & 3;
        float4 v = pa[p];
        As[(kq * 4 + 0) * 128 + r] = v.x;
        As[(kq * 4 + 1) * 128 + r] = v.y;
        As[(kq * 4 + 2) * 128 + r] = v.z;
        As[(kq * 4 + 3) * 128 + r] = v.w;
        int kk = idx >> 5, n4 = idx & 31;
        *(float4*)&Bs[kk * 128 + n4 * 4] = pw[p];
    }
}

__global__ void __launch_bounds__(256, 2)
k_gemm19(const float* __restrict__ A, const float* __restrict__ W,
         const float* __restrict__ bias,
         const float* __restrict__ gm, const float* __restrict__ bt,
         float* __restrict__ out) {
    __shared__ float As[2][16 * 128];
    __shared__ float Bs[2][16 * 128];
    const int tid = threadIdx.x;
    const int tx = tid & 15;
    const int ty = tid >> 4;
    const int m0 = blockIdx.x * 128;

    ull acc[8][4];
#pragma unroll
    for (int r = 0; r < 8; r++)
#pragma unroll
        for (int c = 0; c < 4; c++) acc[r][c] = 0ull;

    float4 pa[2], pw[2];
    ld_tiles19(A, W, m0, 0, tid, pa, pw);
    st_tiles19(As[0], Bs[0], tid, pa, pw);
    __syncthreads();

#pragma unroll
    for (int kt = 0; kt < 2; kt++) {
        const float* Ac = As[kt & 1];
        const float* Bc = Bs[kt & 1];
        if (kt == 0) ld_tiles19(A, W, m0, 16, tid, pa, pw);
#pragma unroll
        for (int k = 0; k < 16; k++) {
            float4 a0 = *(const float4*)&Ac[k * 128 + ty * 8];
            float4 a1 = *(const float4*)&Ac[k * 128 + ty * 8 + 4];
            float4 b0 = *(const float4*)&Bc[k * 128 + tx * 8];
            float4 b1 = *(const float4*)&Bc[k * 128 + tx * 8 + 4];
            ull bp0 = pk2(b0.x, b0.y), bp1 = pk2(b0.z, b0.w);
            ull bp2 = pk2(b1.x, b1.y), bp3 = pk2(b1.z, b1.w);
            float arr[8] = {a0.x, a0.y, a0.z, a0.w, a1.x, a1.y, a1.z, a1.w};
#pragma unroll
            for (int r = 0; r < 8; r++) {
                ull ap = dup2(arr[r]);
                ffma2(acc[r][0], ap, bp0);
                ffma2(acc[r][1], ap, bp1);
                ffma2(acc[r][2], ap, bp2);
                ffma2(acc[r][3], ap, bp3);
            }
        }
        if (kt == 0) st_tiles19(As[1], Bs[1], tid, pa, pw);
        __syncthreads();
    }

    float4 bb0 = *(const float4*)&bias[tx * 8];
    float4 bb1 = *(const float4*)&bias[tx * 8 + 4];
    float bv[8] = {bb0.x, bb0.y, bb0.z, bb0.w, bb1.x, bb1.y, bb1.z, bb1.w};
    float cS[8], cQ[8];
#pragma unroll
    for (int c = 0; c < 8; c++) { cS[c] = 0.f; cQ[c] = 0.f; }
#pragma unroll
    for (int r = 0; r < 8; r++) {
        int grow = m0 + ty * 8 + r;
        if (grow < NN) {
            float2 p0 = upk(acc[r][0]), p1 = upk(acc[r][1]);
            float2 p2 = upk(acc[r][2]), p3 = upk(acc[r][3]);
            float v[8] = {p0.x, p0.y, p1.x, p1.y, p2.x, p2.y, p3.x, p3.y};
#pragma unroll
            for (int c = 0; c < 8; c++) {
                v[c] += bv[c];
                cS[c] += v[c]; cQ[c] += v[c] * v[c];
            }
            *(float4*)&out[(size_t)grow * HD + tx * 8]     = make_float4(v[0], v[1], v[2], v[3]);
            *(float4*)&out[(size_t)grow * HD + tx * 8 + 4] = make_float4(v[4], v[5], v[6], v[7]);
        }
    }
    stats_epilogue<GB_H>(As[0], cS, cQ, tid, tx, ty, gm, bt);
}

// ---------------- pooling / classifier ----------------
__global__ void k_pool(const float* __restrict__ x) {
    __shared__ float ps[4][128];
    __shared__ float pm[4][128];
    int b = blockIdx.x;
    int rg = threadIdx.x >> 7, c = threadIdx.x & 127;
    int st = g_gstart[b], en = g_gstart[b + 1];
    float s = 0.f, m = -INFINITY;
    for (int r = st + rg; r < en; r += 4) {
        float v = x[(size_t)r * HD + c];
        s += v;
        m = fmaxf(m, v);
    }
    ps[rg][c] = s;
    pm[rg][c] = m;
    __syncthreads();
    if (rg == 0) {
        float ss = ps[0][c] + ps[1][c] + ps[2][c] + ps[3][c];
        float mm = fmaxf(fmaxf(pm[0][c], pm[1][c]), fmaxf(pm[2][c], pm[3][c]));
        int cnt = en - st;
        g_pooled[b * 256 + c] = ss / (float)(cnt > 0 ? cnt : 1);
        g_pooled[b * 256 + 128 + c] = mm;
    }
}

__global__ void k_cls(const float* __restrict__ g0,
                      const float* __restrict__ cw1, const float* __restrict__ cb1,
                      const float* __restrict__ cgm, const float* __restrict__ cbt,
                      const float* __restrict__ cw2, const float* __restrict__ cb2,
                      float* __restrict__ out) {
    __shared__ float zrow[8][264];
    __shared__ float h1[64][128];
    __shared__ float lg[64][2];
    int c = threadIdx.x;  // <<<1,128>>>

    for (int r0 = 0; r0 < 64; r0 += 8) {
        for (int idx = c; idx < 8 * 264; idx += 128) {
            int rr = idx / 264, k = idx - rr * 264;
            int r = r0 + rr;
            zrow[rr][k] = (k < 256) ? g_pooled[r * 256 + k] : g0[r * GF + (k - 256)];
        }
        __syncthreads();
        float acc[8];
#pragma unroll
        for (int rr = 0; rr < 8; rr++) acc[rr] = 0.f;
        for (int k = 0; k < 264; ++k) {
            float w = cw1[k * HD + c];
#pragma unroll
            for (int rr = 0; rr < 8; rr++) acc[rr] += zrow[rr][k] * w;
        }
        float bias = cb1[c];
#pragma unroll
        for (int rr = 0; rr < 8; rr++) h1[r0 + rr][c] = elu01(acc[rr] + bias);
        __syncthreads();
    }

    float s = 0.f, sq = 0.f;
    for (int r = 0; r < 64; r++) {
        float v = h1[r][c];
        s += v;
        sq += v * v;
    }
    float mean = s * (1.f / 64.f);
    float var = sq * (1.f / 64.f) - mean * mean;
    float a = cgm[c] * rsqrtf(var + BN_EPS);
    float bb = cbt[c] - mean * a;
    for (int r = 0; r < 64; r++) h1[r][c] = h1[r][c] * a + bb;
    __syncthreads();

    {
        int r = c >> 1, cls = c & 1;
        float l = cb2[cls];
        for (int k = 0; k < 128; k++) l += h1[r][k] * cw2[k * 2 + cls];
        lg[r][cls] = l;
    }
    __syncthreads();
    {
        int r = c >> 1, cls = c & 1;
        float l0 = lg[r][0], l1 = lg[r][1];
        float mx = fmaxf(l0, l1);
        float e0 = expf(l0 - mx), e1 = expf(l1 - mx);
        out[r * 2 + cls] = ((cls == 0) ? e0 : e1) / (e0 + e1);
    }
}

// ---------------- launch ----------------
extern "C" void kernel_launch(void* const* d_in, const int* in_sizes, int n_in,
                              void* d_out, int out_size) {
    const float* h0     = (const float*)d_in[0];
    const float* coord0 = (const float*)d_in[1];
    const float* g0     = (const float*)d_in[2];
    const int*   eidx   = (const int*)  d_in[3];
    const int*   batch  = (const int*)  d_in[4];
    const float* w1_0 = (const float*)d_in[5];
    const float* b1_0 = (const float*)d_in[6];
    const float* gm_0 = (const float*)d_in[7];
    const float* bt_0 = (const float*)d_in[8];
    const float* w2_0 = (const float*)d_in[9];
    const float* b2_0 = (const float*)d_in[10];
    const float* w1_r = (const float*)d_in[11];
    const float* b1_r = (const float*)d_in[12];
    const float* gm_r = (const float*)d_in[13];
    const float* bt_r = (const float*)d_in[14];
    const float* w2_r = (const float*)d_in[15];
    const float* b2_r = (const float*)d_in[16];
    const float* cw1  = (const float*)d_in[17];
    const float* cb1  = (const float*)d_in[18];
    const float* cgm  = (const float*)d_in[19];
    const float* cbt  = (const float*)d_in[20];
    const float* cw2  = (const float*)d_in[21];
    const float* cb2  = (const float*)d_in[22];

    const int* src = eidx;
    const int* dst = eidx + NE;

    float *xa19, *h, *xagg, *xA, *xB;
    cudaGetSymbolAddress((void**)&xa19, g_xa19);
    cudaGetSymbolAddress((void**)&h,    g_h);
    cudaGetSymbolAddress((void**)&xagg, g_xagg);
    cudaGetSymbolAddress((void**)&xA,   g_xA);
    cudaGetSymbolAddress((void**)&xB,   g_xB);

    cudaFuncSetAttribute(k_gemmH<true, false, true>,
                         cudaFuncAttributeMaxDynamicSharedMemorySize, GH_SMEM);
    cudaFuncSetAttribute(k_gemmH<false, true, false>,
                         cudaFuncAttributeMaxDynamicSharedMemorySize, GH_SMEM);

    // ---- CSR build (+ zeroing fused into k_bounds) ----
    k_bounds<<<(NN + 255) / 256, 256>>>(batch);
    k_deg<<<(NE + 255) / 256, 256>>>(dst);
    k_scanA<<<SCAN_NBLK, SCAN_BS>>>();
    k_scanC<<<(NN + 255) / 256, 256>>>();
    k_fill<<<(NE + 255) / 256, 256>>>(src, dst);

    // ---- layer 0 ----
    k_concat<<<(NN * F20 + 255) / 256, 256>>>(h0, coord0);
    k_gather19<<<(NN * 5 + 255) / 256, 256>>>();
    k_gemm19<<<GB_H, 256>>>(xa19, w1_0, b1_0, gm_0, bt_0, h);
    k_gemmH<true, false, true><<<GB_H, 256, GH_SMEM>>>(h, w2_0, b2_0, nullptr, nullptr, xA);

    // ---- layers 1..2 ----
    for (int i = 0; i < 2; i++) {
        const float* xin = (i == 0) ? xA : xB;
        float* xout      = (i == 0) ? xB : xA;
        k_gatherH<<<(NN + 7) / 8, 256>>>(xin, xagg);
        k_gemmH<false, true, false><<<GB_H, 256, GH_SMEM>>>(
            xagg, w1_r + i * HD * HD, b1_r + i * HD, gm_r + i * HD, bt_r + i * HD, h);
        k_gemmH<true, false, true><<<GB_H, 256, GH_SMEM>>>(
            h, w2_r + i * HD * HD, b2_r + i * HD, nullptr, nullptr, xout);
    }

    // ---- pooling + classifier ----
    k_pool<<<NB, 512>>>(xA);
    k_cls<<<1, 128>>>(g0, cw1, cb1, cgm, cbt, cw2, cb2, (float*)d_out);
}